// round 4
// baseline (speedup 1.0000x reference)
#include <cuda_runtime.h>

#define DIM 128
#define MAX_NODES 65536
#define NT 256
#define EPW 8  // edges per warp

__device__ float g_Q[MAX_NODES * 2 * DIM];
__device__ int g_idx64;

__device__ __forceinline__ unsigned long long pack2(float lo, float hi) {
    unsigned long long r;
    asm("mov.b64 %0, {%1, %2};" : "=l"(r) : "f"(lo), "f"(hi));
    return r;
}
__device__ __forceinline__ float2 unpack2(unsigned long long v) {
    float2 f;
    asm("mov.b64 {%0, %1}, %2;" : "=f"(f.x), "=f"(f.y) : "l"(v));
    return f;
}
__device__ __forceinline__ void ffma2(unsigned long long& d, unsigned long long a,
                                      unsigned long long b) {
    asm("fma.rn.f32x2 %0, %1, %2, %0;" : "+l"(d) : "l"(a), "l"(b));
}

// ---------------------------------------------------------------------------
__global__ void detect_idx_kernel(const unsigned int* __restrict__ w) {
    __shared__ int s_any;
    if (threadIdx.x == 0) s_any = 0;
    __syncthreads();
    int found = 0;
    for (int i = threadIdx.x; i < 4096; i += blockDim.x)
        if (w[2 * i + 1] != 0u) found = 1;
    if (found) atomicOr(&s_any, 1);
    __syncthreads();
    if (threadIdx.x == 0) g_idx64 = (s_any == 0) ? 1 : 0;
}

// ---------------------------------------------------------------------------
// Precompute Q[n][c]: 32 nodes/block (16 node-pairs, f32x2).
// Per d: 1 coalesced LDG (w) + 8 broadcast LDS.128 + 16 FFMA2.
// ---------------------------------------------------------------------------
__global__ __launch_bounds__(256)
void precompute_kernel(const float* __restrict__ nf, const float* __restrict__ centroid,
                       const float* __restrict__ W1, int n_nodes, int npg) {
    __shared__ float s_resT[DIM * 32];
    const int base = blockIdx.x * 32;
    const int t = threadIdx.x;
    for (int idx = t; idx < 32 * DIM; idx += 256) {
        int node = base + (idx >> 7);
        int d = idx & 127;
        float v = 0.f;
        if (node < n_nodes)
            v = nf[(size_t)node * DIM + d] - centroid[(size_t)(node / npg) * DIM + d];
        s_resT[d * 32 + (idx >> 7)] = v;
    }
    __syncthreads();

    const int c = t;  // 0..255
    const float* wcol = (c < DIM) ? (W1 + DIM * DIM + c)
                                  : (W1 + 2 * DIM * DIM + (c - DIM));
    unsigned long long acc[16];
#pragma unroll
    for (int p = 0; p < 16; p++) acc[p] = 0ull;

#pragma unroll 2
    for (int d = 0; d < DIM; d++) {
        float w = __ldg(wcol + (size_t)d * DIM);
        unsigned long long wp = pack2(w, w);
        const ulonglong2* ap = (const ulonglong2*)(s_resT + d * 32);
#pragma unroll
        for (int q = 0; q < 8; q++) {
            ulonglong2 a = ap[q];
            ffma2(acc[2 * q], a.x, wp);
            ffma2(acc[2 * q + 1], a.y, wp);
        }
    }
#pragma unroll
    for (int p = 0; p < 16; p++) {
        float2 v = unpack2(acc[p]);
        int n0 = base + 2 * p;
        if (n0 < n_nodes)     g_Q[(size_t)n0 * 256 + c] = v.x;
        if (n0 + 1 < n_nodes) g_Q[(size_t)(n0 + 1) * 256 + c] = v.y;
    }
}

// ---------------------------------------------------------------------------
// Edge kernel: 8 edges/warp, k-pair f32x2. Per warp-d: one LDS.128 of W
// amortized over 8 edges -> smem crossbar demand 72 B/cyc/SM (< 128),
// issue 33 slots vs 32 fma-pipe cyc: FMA-bound.
// ---------------------------------------------------------------------------
__global__ __launch_bounds__(NT)
void edge_kernel(const float* __restrict__ nf, const void* __restrict__ ei,
                 const float* __restrict__ W1, const float* __restrict__ b1,
                 const float* __restrict__ W2, const float* __restrict__ b2,
                 float* __restrict__ out, int E) {
    extern __shared__ float smem[];
    float* sW  = smem;                 // 128*128
    float* sB1 = sW + DIM * DIM;       // 128
    float* sW2 = sB1 + DIM;            // 128
    float* sA  = sW2 + DIM;            // 8 warps * EPW * 128

    const int t = threadIdx.x;
#pragma unroll 4
    for (int i = t; i < DIM * DIM / 4; i += NT)
        ((float4*)sW)[i] = ((const float4*)W1)[i];
    if (t < DIM) { sB1[t] = b1[t]; sW2[t] = W2[t]; }
    __syncthreads();

    const float bias2 = b2[0];
    const int warp = t >> 5;
    const int lane = t & 31;
    const int mode64 = g_idx64;
    const long long* ei64 = (const long long*)ei;
    const int* ei32 = (const int*)ei;
    float* aw = sA + warp * (EPW * DIM);
    const int k0 = lane * 4;
    const float4 b1v = *(const float4*)(sB1 + k0);
    const float4 w2v = *(const float4*)(sW2 + k0);

    const int eper_blk = 8 * EPW;  // 64
    const int tiles = (E + eper_blk - 1) / eper_blk;
    for (int tile = blockIdx.x; tile < tiles; tile += gridDim.x) {
        const int e0 = tile * eper_blk + warp * EPW;

        int src[EPW], dst[EPW];
#pragma unroll
        for (int e = 0; e < EPW; e++) {
            int eid = e0 + e;
            if (eid < E) {
                if (mode64) { src[e] = (int)ei64[eid]; dst[e] = (int)ei64[E + eid]; }
                else        { src[e] = ei32[eid];      dst[e] = ei32[E + eid]; }
            } else { src[e] = 0; dst[e] = 0; }
        }

        // gather |nf[dst]-nf[src]| into per-warp smem (coalesced, conflict-free)
#pragma unroll
        for (int e = 0; e < EPW; e++) {
            const float* pi = nf + (size_t)dst[e] * DIM;
            const float* pj = nf + (size_t)src[e] * DIM;
#pragma unroll
            for (int r = 0; r < 4; r++) {
                int d = lane + 32 * r;
                aw[e * DIM + d] = fabsf(pi[d] - pj[d]);
            }
        }
        __syncwarp();

        // acc init = Q[dst][k] + Q[src][128+k] + b1[k], k-pair packed
        unsigned long long acc[EPW][2];
#pragma unroll
        for (int e = 0; e < EPW; e++) {
            const float4 qb = *(const float4*)(g_Q + (size_t)dst[e] * 256 + k0);
            const float4 qc = *(const float4*)(g_Q + (size_t)src[e] * 256 + 128 + k0);
            acc[e][0] = pack2(qb.x + qc.x + b1v.x, qb.y + qc.y + b1v.y);
            acc[e][1] = pack2(qb.z + qc.z + b1v.z, qb.w + qc.w + b1v.w);
        }

        // 128-d matvec: W k-pairs via one LDS.128 per d, a via broadcast LDS
#pragma unroll 2
        for (int d = 0; d < DIM; d++) {
            const ulonglong2 wp = *(const ulonglong2*)(sW + d * DIM + k0);
#pragma unroll
            for (int e = 0; e < EPW; e++) {
                float a = aw[e * DIM + d];
                unsigned long long apk = pack2(a, a);
                ffma2(acc[e][0], apk, wp.x);
                ffma2(acc[e][1], apk, wp.y);
            }
        }

        // epilogue: relu, dot W2, warp reduce, store
        float s[EPW];
#pragma unroll
        for (int e = 0; e < EPW; e++) {
            float2 h01 = unpack2(acc[e][0]);
            float2 h23 = unpack2(acc[e][1]);
            s[e] = fmaxf(h01.x, 0.f) * w2v.x
                 + fmaxf(h01.y, 0.f) * w2v.y
                 + fmaxf(h23.x, 0.f) * w2v.z
                 + fmaxf(h23.y, 0.f) * w2v.w;
        }
#pragma unroll
        for (int off = 16; off > 0; off >>= 1) {
#pragma unroll
            for (int e = 0; e < EPW; e++)
                s[e] += __shfl_down_sync(0xffffffffu, s[e], off);
        }
        if (lane == 0) {
#pragma unroll
            for (int e = 0; e < EPW; e++)
                if (e0 + e < E) out[e0 + e] = s[e] + bias2;
        }
        __syncwarp();
    }
}

// ---------------------------------------------------------------------------
extern "C" void kernel_launch(void* const* d_in, const int* in_sizes, int n_in,
                              void* d_out, int out_size) {
    const float *nf = 0, *centroid = 0, *W1 = 0, *b1 = 0, *W2 = 0, *b2 = 0;
    const void* ei = 0;
    int nf_elems = 0, cen_elems = 0;
    int last_size1 = -1;

    for (int i = 0; i < n_in; i++) {
        int s = in_sizes[i];
        if (s == 1) { last_size1 = i; continue; }
        if (s == 128) {
            if (!b1) b1 = (const float*)d_in[i];
            else     W2 = (const float*)d_in[i];
            continue;
        }
        if (s == 2048) { centroid = (const float*)d_in[i]; cen_elems = s; continue; }
        if (s == 49152) { W1 = (const float*)d_in[i]; continue; }
        if (s == 2 * out_size) { ei = d_in[i]; continue; }
        if (s > nf_elems) { nf = (const float*)d_in[i]; nf_elems = s; }
    }
    if (last_size1 >= 0) b2 = (const float*)d_in[last_size1];

    const int E = out_size;
    const int n_nodes = nf_elems / DIM;
    const int bs = cen_elems / DIM;
    const int npg = n_nodes / (bs > 0 ? bs : 1);

    precompute_kernel<<<(n_nodes + 31) / 32, 256>>>(nf, centroid, W1, n_nodes, npg);

    detect_idx_kernel<<<1, 256>>>((const unsigned int*)ei);

    const size_t shbytes = (size_t)(DIM * DIM + DIM + DIM + 8 * EPW * DIM) * sizeof(float);
    cudaFuncSetAttribute(edge_kernel, cudaFuncAttributeMaxDynamicSharedMemorySize,
                         (int)shbytes);
    edge_kernel<<<2048, NT, shbytes>>>(nf, ei, W1, b1, W2, b2, (float*)d_out, E);
}